// round 14
// baseline (speedup 1.0000x reference)
#include <cuda_runtime.h>
#include <math.h>

// Problem constants
#define BB   8
#define CC_  256
#define HH   96
#define WW   128
#define RR   4
#define DD   9                 // 2R+1
#define HWSZ (HH*WW)           // 12288
#define CHW  (CC_*HWSZ)        // 3145728

// Tiling: 2 co-resident blocks per SM
#define XT   32
#define YT   4
#define KC   4
#define FQH  (YT + 2*RR)       // 12
#define FQW  (XT + 2*RR)       // 40
#define NTHR 288               // 8 xg * 4 yr * 9 dy
#define NCHUNK (CC_/KC)        // 64
#define QG   2                 // fq float4 groups per thread (2nd predicated)

#define FQBUF (KC*FQH*FQW)     // 1920 floats per fq buffer
#define FRBUF (KC*YT*XT)       // 512 floats per fr buffer

// Packed fp32x2 helpers (sm_103a)
#define PACK2(d, lo, hi) asm("mov.b64 %0, {%1, %2};" : "=l"(d) : "f"(lo), "f"(hi))
#define FMA2(acc, a, b)  asm("fma.rn.f32x2 %0, %1, %2, %0;" : "+l"(acc) : "l"(a), "l"(b))
#define UNPK2(lo, hi, s) asm("mov.b64 {%0, %1}, %2;" : "=f"(lo), "=f"(hi) : "l"(s))

// ---------------------------------------------------------------------------
__device__ __forceinline__ void stage_chunk(
    float* fq_buf, float* fr_buf,
    const float4* vq, float4 vr,
    const int* qdst, const bool* qok, int rdst, bool has_r,
    float4* sq, float4& sr)
{
#pragma unroll
    for (int k = 0; k < QG; k++) {
        if (!qok[k]) continue;
        float4 v = vq[k];
        float* d = fq_buf + qdst[k];
        d[0] = v.x; d[1] = v.y; d[2] = v.z; d[3] = v.w;
        sq[k].x = fmaf(v.x, v.x, sq[k].x);
        sq[k].y = fmaf(v.y, v.y, sq[k].y);
        sq[k].z = fmaf(v.z, v.z, sq[k].z);
        sq[k].w = fmaf(v.w, v.w, sq[k].w);
    }
    if (has_r) {
        float* d = fr_buf + rdst;
        d[0] = vr.x; d[1] = vr.y; d[2] = vr.z; d[3] = vr.w;
        sr.x = fmaf(vr.x, vr.x, sr.x);
        sr.y = fmaf(vr.y, vr.y, sr.y);
        sr.z = fmaf(vr.z, vr.z, sr.z);
        sr.w = fmaf(vr.w, vr.w, sr.w);
    }
}

// ---------------------------------------------------------------------------
// Fused correlation + norms. 2 blocks/SM; double-buffered smem (1 barrier
// per chunk), register prefetch, packed f32x2 FMA inner loop.
// ---------------------------------------------------------------------------
__global__ __launch_bounds__(NTHR, 2) void corr_kernel(const float* __restrict__ fr,
                                                       const float* __restrict__ fq,
                                                       float* __restrict__ out)
{
    __shared__ float s_fq[2 * FQBUF];     // 15360 B
    __shared__ float s_fr[2 * FRBUF];     //  4096 B
    __shared__ float s_sq[FQH * FQW];     //  1920 B
    __shared__ float s_sr[YT * XT];       //   512 B

    const int tid = threadIdx.x;
    const int xg  = tid & 7;           // 0..7 -> pixels xg*4..xg*4+3
    const int yr  = (tid >> 3) & 3;    // 0..3
    const int dy  = tid >> 5;          // 0..8 (one dy per warp)

    const int x0 = blockIdx.x * XT;
    const int y0 = blockIdx.y * YT;
    const int b  = blockIdx.z;

    // zero norm-sum arrays
    for (int e = tid; e < FQH * FQW; e += NTHR) s_sq[e] = 0.f;
    if (tid < YT * XT) s_sr[tid] = 0.f;

    // ---- staging descriptors (fixed per thread)
    const float* qsrc[QG];
    int qdst[QG], qslot[QG];
    bool qok[QG];
#pragma unroll
    for (int k = 0; k < QG; k++) {
        int g = tid + k * NTHR;
        qok[k] = (g < KC * FQH * (FQW / 4));            // < 480
        int q4 = g % (FQW / 4);                         // 0..9
        int r2 = g / (FQW / 4);
        int ry = r2 % FQH;                              // 0..11
        int cc = r2 / FQH;                              // 0..3
        int gy = y0 + ry - RR;
        int gx = x0 + q4 * 4 - RR;
        bool inb = ((unsigned)gy < (unsigned)HH) && ((unsigned)gx < (unsigned)(WW - 3));
        qsrc[k]  = inb ? fq + (size_t)b * CHW + (size_t)cc * HWSZ + gy * WW + gx : nullptr;
        qdst[k]  = (cc * FQH + ry) * FQW + q4 * 4;
        qslot[k] = ry * FQW + q4 * 4;
    }
    const float* rsrc = nullptr;
    int rdst = 0, rslot = 0;
    const bool has_r = (tid < KC * YT * (XT / 4));      // < 128
    if (has_r) {
        int cc  = tid >> 5;            // 0..3
        int rem = tid & 31;
        int yy  = rem >> 3;            // 0..3
        int xq  = rem & 7;             // 0..7
        rsrc  = fr + (size_t)b * CHW + (size_t)cc * HWSZ + (y0 + yy) * WW + x0 + xq * 4;
        rdst  = (cc * YT + yy) * XT + xq * 4;
        rslot = yy * XT + xq * 4;
    }

    // norm partial sums
    float4 sq[QG];
#pragma unroll
    for (int k = 0; k < QG; k++) sq[k] = make_float4(0.f, 0.f, 0.f, 0.f);
    float4 sr = make_float4(0.f, 0.f, 0.f, 0.f);

    // packed accumulators: acc2[dx][0] = pixels 0,1 ; acc2[dx][1] = pixels 2,3
    unsigned long long acc2[DD][2];
#pragma unroll
    for (int d = 0; d < DD; d++) { acc2[d][0] = 0ull; acc2[d][1] = 0ull; }

    // ---- prefetch + stage chunk 0 into buffer 0
    float4 vq[QG], vr = make_float4(0.f, 0.f, 0.f, 0.f);
#pragma unroll
    for (int k = 0; k < QG; k++)
        vq[k] = qsrc[k] ? *reinterpret_cast<const float4*>(qsrc[k])
                        : make_float4(0.f, 0.f, 0.f, 0.f);
    if (rsrc) vr = *reinterpret_cast<const float4*>(rsrc);
    stage_chunk(s_fq, s_fr, vq, vr, qdst, qok, rdst, has_r, sq, sr);
    __syncthreads();

    const int qoff = (yr + dy) * FQW + xg * 4;
    const int aoff = yr * XT + xg * 4;

    for (int ch = 0; ch < NCHUNK; ch++) {
        const int buf  = ch & 1;
        const int nbuf = buf ^ 1;

        // ---- prefetch next chunk (latency hidden by compute)
        if (ch + 1 < NCHUNK) {
            size_t off = (size_t)(ch + 1) * KC * HWSZ;
#pragma unroll
            for (int k = 0; k < QG; k++)
                vq[k] = qsrc[k] ? *reinterpret_cast<const float4*>(qsrc[k] + off)
                                : make_float4(0.f, 0.f, 0.f, 0.f);
            if (rsrc) vr = *reinterpret_cast<const float4*>(rsrc + off);
        }

        const float* abase = s_fr + buf * FRBUF + aoff;
        const float* qbase = s_fq + buf * FQBUF + qoff;

        // ---- compute: per channel 4 LDS.128 -> packs + 18 FFMA2
#pragma unroll
        for (int cc = 0; cc < KC; cc++) {
            float4 a4 = *reinterpret_cast<const float4*>(abase + cc * (YT * XT));
            const float* qp_ = qbase + cc * (FQH * FQW);
            float4 q0 = *reinterpret_cast<const float4*>(qp_ + 0);
            float4 q1 = *reinterpret_cast<const float4*>(qp_ + 4);
            float4 q2 = *reinterpret_cast<const float4*>(qp_ + 8);
            float q[12] = {q0.x, q0.y, q0.z, q0.w,
                           q1.x, q1.y, q1.z, q1.w,
                           q2.x, q2.y, q2.z, q2.w};

            unsigned long long a01, a23, qp2[11];
            PACK2(a01, a4.x, a4.y);
            PACK2(a23, a4.z, a4.w);
#pragma unroll
            for (int k = 0; k < 11; k++) PACK2(qp2[k], q[k], q[k + 1]);

#pragma unroll
            for (int dx = 0; dx < DD; dx++) {
                FMA2(acc2[dx][0], a01, qp2[dx]);
                FMA2(acc2[dx][1], a23, qp2[dx + 2]);
            }
        }

        // ---- stage next chunk into the other buffer (pre-barrier)
        if (ch + 1 < NCHUNK)
            stage_chunk(s_fq + nbuf * FQBUF, s_fr + nbuf * FRBUF,
                        vq, vr, qdst, qok, rdst, has_r, sq, sr);

        __syncthreads();
    }

    // ---- combine norm partials (KC contributors per slot)
#pragma unroll
    for (int k = 0; k < QG; k++) {
        if (!qok[k]) continue;
        atomicAdd(&s_sq[qslot[k] + 0], sq[k].x);
        atomicAdd(&s_sq[qslot[k] + 1], sq[k].y);
        atomicAdd(&s_sq[qslot[k] + 2], sq[k].z);
        atomicAdd(&s_sq[qslot[k] + 3], sq[k].w);
    }
    if (has_r) {
        atomicAdd(&s_sr[rslot + 0], sr.x);
        atomicAdd(&s_sr[rslot + 1], sr.y);
        atomicAdd(&s_sr[rslot + 2], sr.z);
        atomicAdd(&s_sr[rslot + 3], sr.w);
    }
    __syncthreads();

    for (int e = tid; e < FQH * FQW; e += NTHR)
        s_sq[e] = 1.0f / fmaxf(sqrtf(s_sq[e]), 1e-12f);
    if (tid < YT * XT)
        s_sr[tid] = (1.0f / 256.0f) / fmaxf(sqrtf(s_sr[tid]), 1e-12f);
    __syncthreads();

    // ---- epilogue
    const int gy = y0 + yr;
    float ir[4];
#pragma unroll
    for (int i = 0; i < 4; i++) ir[i] = s_sr[yr * XT + xg * 4 + i];

    float iq[12];
    {
        const float* iqp = s_sq + (yr + dy) * FQW + xg * 4;
#pragma unroll
        for (int i = 0; i < 12; i++) iq[i] = iqp[i];
    }

#pragma unroll
    for (int dx = 0; dx < DD; dx++) {
        float p0, p1, p2, p3;
        UNPK2(p0, p1, acc2[dx][0]);
        UNPK2(p2, p3, acc2[dx][1]);
        float4 o;
        o.x = p0 * ir[0] * iq[0 + dx];
        o.y = p1 * ir[1] * iq[1 + dx];
        o.z = p2 * ir[2] * iq[2 + dx];
        o.w = p3 * ir[3] * iq[3 + dx];
        float* op = out + ((size_t)(b * (DD * DD) + dy * DD + dx) * HH + gy) * WW
                        + x0 + xg * 4;
        *reinterpret_cast<float4*>(op) = o;
    }
}

// ---------------------------------------------------------------------------
extern "C" void kernel_launch(void* const* d_in, const int* in_sizes, int n_in,
                              void* d_out, int out_size)
{
    const float* fr = (const float*)d_in[0];
    const float* fq = (const float*)d_in[1];
    float* out = (float*)d_out;

    dim3 grid(WW / XT, HH / YT, BB);   // (4, 24, 8) = 768 blocks
    corr_kernel<<<grid, NTHR>>>(fr, fq, out);
}